// round 6
// baseline (speedup 1.0000x reference)
#include <cuda_runtime.h>
#include <math.h>

typedef unsigned long long u64;

#define NTH 256
#define LDA 68     // bufA stride (floats)
#define LDB 132    // bufB/bufC stride

// float offsets in dynamic smem
#define F_STG   0         // 1600   to_grid (64x25)
#define F_A     1600      // 8704   bufA: g / g3 (128 x LDA)
#define F_B     10304     // 16896  bufB: g1 (128 x LDB); sxn aliases start; hb aliases start later
#define F_C     27200     // 16896  bufC: g2 (128 x LDB); sh aliases start
#define F_W     44096     // 8192   staged weights (one stage / half-stage)
#define F_GAT   52288     // 128
#define F_RED   52416     // 64
#define SMEM_FLOATS 52480 // 209920 bytes

__device__ __constant__ int c_deg[25] = {
    0, 1,1,1, 2,2,2,2,2, 3,3,3,3,3,3,3, 4,4,4,4,4,4,4,4,4
};
__device__ __constant__ float c_bw[25] = {
    0.f,
    1.f/12.f, 1.f/12.f, 1.f/12.f,
    1.f/20.f, 1.f/20.f, 1.f/20.f, 1.f/20.f, 1.f/20.f,
    1.f/28.f, 1.f/28.f, 1.f/28.f, 1.f/28.f, 1.f/28.f, 1.f/28.f, 1.f/28.f,
    1.f/36.f, 1.f/36.f, 1.f/36.f, 1.f/36.f, 1.f/36.f, 1.f/36.f, 1.f/36.f, 1.f/36.f, 1.f/36.f
};

__device__ __forceinline__ u64 ffma2(u64 a, u64 b, u64 c) {
    u64 d;
    asm("fma.rn.f32x2 %0, %1, %2, %3;" : "=l"(d) : "l"(a), "l"(b), "l"(c));
    return d;
}
__device__ __forceinline__ u64 dup2(float x) {
    u64 r; asm("mov.b64 %0, {%1, %1};" : "=l"(r) : "f"(x)); return r;
}
__device__ __forceinline__ float2 unpk(u64 v) {
    float2 f; asm("mov.b64 {%0, %1}, %2;" : "=f"(f.x), "=f"(f.y) : "l"(v)); return f;
}
__device__ __forceinline__ float silu_f(float v) {
    return v * (1.f / (1.f + __expf(-v)));
}

// Staged-weight GEMM accumulate: rows [rowbase, rowbase+8), cols tx*(2*NQ)..,
// K-range [0,kcnt) reading A at column offset kAoff.
template<int NQ>
__device__ __forceinline__ void gemm_acc(
    const float* __restrict__ A, int lda, int kcnt, int kAoff,
    const float* __restrict__ B, int ldb, int tx, int rowbase,
    u64 acc[8][NQ])
{
    #pragma unroll 2
    for (int k0 = 0; k0 < kcnt; k0 += 4) {
        float4 av[8];
        #pragma unroll
        for (int r = 0; r < 8; r++)
            av[r] = *reinterpret_cast<const float4*>(A + (rowbase + r) * lda + kAoff + k0);
        #pragma unroll
        for (int kk = 0; kk < 4; kk++) {
            u64 b[NQ];
            #pragma unroll
            for (int q = 0; q < NQ; q += 2) {
                ulonglong2 bw = *reinterpret_cast<const ulonglong2*>(
                    B + (k0 + kk) * ldb + tx * (NQ * 2) + q * 2);
                b[q] = bw.x; b[q + 1] = bw.y;
            }
            #pragma unroll
            for (int r = 0; r < 8; r++) {
                const float* ap = reinterpret_cast<const float*>(&av[r]);
                u64 a = dup2(ap[kk]);
                #pragma unroll
                for (int q = 0; q < NQ; q++)
                    acc[r][q] = ffma2(a, b[q], acc[r][q]);
            }
        }
    }
}

__global__ __launch_bounds__(NTH, 1)
void fused_equi(
    const float* __restrict__ x,
    const float* __restrict__ nl0w,
    const float* __restrict__ nl0b,
    const float* __restrict__ affw,
    const float* __restrict__ l1w,
    const float* __restrict__ l1b,
    const float* __restrict__ scw,
    const float* __restrict__ scb,
    const float* __restrict__ gw1,
    const float* __restrict__ gw2,
    const float* __restrict__ gw3,
    const float* __restrict__ l2w,
    const float* __restrict__ l2b,
    const float* __restrict__ tg,
    float* __restrict__ out)
{
    extern __shared__ float smf[];
    float* STGm = smf + F_STG;
    float* BA   = smf + F_A;
    float* BB   = smf + F_B;
    float* BC   = smf + F_C;
    float* BW   = smf + F_W;
    float* SGAT = smf + F_GAT;
    float* SRED = smf + F_RED;
    float* SXN  = BB;          // alias (dead before g1 writes BB)
    float* SH   = BC;          // alias (dead before g2 writes BC)
    float* HBUF = BB;          // alias (g1 dead before from_grid writes)

    const int tid = threadIdx.x;
    const int half = tid >> 7, t = tid & 127;
    const long long n2 = blockIdx.x;   // sample-pair index

    // ---------- phase 0: loads ----------
    const float* xin = x + n2 * 3200;
    for (int i = tid; i < 3200; i += NTH) SXN[i] = xin[i];
    for (int i = tid; i < 1600; i += NTH) STGm[i] = tg[i];
    {   // stage W1 (64x128 = 8192 floats)
        float4* d = (float4*)BW; const float4* s = (const float4*)gw1;
        #pragma unroll
        for (int i = tid; i < 2048; i += NTH) d[i] = s[i];
    }
    __syncthreads();

    float* sxn_h = SXN + half * 1600;
    float* sh_h  = SH  + half * 1600;

    // ---------- stats per half ----------
    {
        float s0 = 0.f, q0 = 0.f, fn = 0.f;
        for (int i = t; i < 1600; i += 128) {
            float v = sxn_h[i];
            int m = i >> 6;
            if (m == 0) { s0 += v; q0 += v * v; }
            else        { fn += c_bw[m] * v * v; }
        }
        #pragma unroll
        for (int off = 16; off > 0; off >>= 1) {
            s0 += __shfl_xor_sync(0xffffffffu, s0, off);
            q0 += __shfl_xor_sync(0xffffffffu, q0, off);
            fn += __shfl_xor_sync(0xffffffffu, fn, off);
        }
        int hw = (tid >> 5) & 3, lane = tid & 31;
        if (lane == 0) {
            SRED[half * 32 + hw]      = s0;
            SRED[half * 32 + 8 + hw]  = q0;
            SRED[half * 32 + 16 + hw] = fn;
        }
        __syncthreads();
        if (t == 0) {
            float a = 0.f, b = 0.f, c = 0.f;
            #pragma unroll
            for (int w = 0; w < 4; w++) {
                a += SRED[half * 32 + w];
                b += SRED[half * 32 + 8 + w];
                c += SRED[half * 32 + 16 + w];
            }
            float mu  = a * (1.f / 64.f);
            float var = b * (1.f / 64.f) - mu * mu;
            SRED[half * 32 + 24] = mu;
            SRED[half * 32 + 25] = rsqrtf(var + 1e-5f);
            SRED[half * 32 + 26] = rsqrtf(c * (1.f / 64.f) + 1e-5f);
        }
        __syncthreads();
    }
    const float mu   = SRED[half * 32 + 24];
    const float rstd = SRED[half * 32 + 25];
    const float inv  = SRED[half * 32 + 26];

    // ---------- normalize ----------
    for (int i = t; i < 1600; i += 128) {
        int m = i >> 6, cc = i & 63;
        float v = sxn_h[i];
        if (m == 0) v = (v - mu) * rstd * nl0w[cc] + nl0b[cc];
        else        v = v * inv * affw[(c_deg[m] - 1) * 64 + cc];
        sxn_h[i] = v;
    }
    __syncthreads();

    // ---------- gating ----------
    if (t < 64) {
        float acc = scb[t];
        #pragma unroll 8
        for (int i = 0; i < 64; i++) acc += sxn_h[i] * scw[i * 64 + t];
        SGAT[half * 64 + t] = silu_f(acc);
    }

    // ---------- lin1: h = xn @ lin1_w[deg] (+b row0) ----------
    {
        const int j2 = t & 31, grp = t >> 5;   // 4 groups, slots +0,+4,+8
        for (int l = 0; l < 5; l++) {
            const int base = l * l, cnt = 2 * l + 1;
            const int r0 = base + grp, r1 = r0 + 4, r2 = r1 + 4;
            const bool b0 = grp < cnt, b1 = grp + 4 < cnt, b2 = grp + 8 < cnt;
            u64 a0 = 0, a1 = 0, a2 = 0;
            const float* w = l1w + l * 4096 + j2 * 2;
            #pragma unroll 4
            for (int i = 0; i < 64; i++) {
                u64 wv = *reinterpret_cast<const u64*>(w + i * 64);
                if (b0) a0 = ffma2(dup2(sxn_h[r0 * 64 + i]), wv, a0);
                if (b1) a1 = ffma2(dup2(sxn_h[r1 * 64 + i]), wv, a1);
                if (b2) a2 = ffma2(dup2(sxn_h[r2 * 64 + i]), wv, a2);
            }
            if (b0) {
                float2 f = unpk(a0);
                if (r0 == 0) { f.x += l1b[j2 * 2]; f.y += l1b[j2 * 2 + 1]; }
                *reinterpret_cast<float2*>(sh_h + r0 * 64 + j2 * 2) = f;
            }
            if (b1) *reinterpret_cast<float2*>(sh_h + r1 * 64 + j2 * 2) = unpk(a1);
            if (b2) *reinterpret_cast<float2*>(sh_h + r2 * 64 + j2 * 2) = unpk(a2);
        }
    }
    __syncthreads();

    const int ty = tid >> 4, tx = tid & 15;   // (16,16): rows ty*8.., 8 per thread
    const int rowbase = ty * 8;

    // ---------- to_grid: g[R, c] = sum_m tg[s,m] h[half_R][m,c] -> bufA ----------
    {
        const float* shh = SH + (ty >= 8 ? 1600 : 0);
        const int sbase = (ty & 7) * 8;
        u64 acc[8][2] = {};
        for (int m = 0; m < 25; m++) {
            u64 bv0 = *reinterpret_cast<const u64*>(shh + m * 64 + tx * 4);
            u64 bv1 = *reinterpret_cast<const u64*>(shh + m * 64 + tx * 4 + 2);
            #pragma unroll
            for (int r = 0; r < 8; r++) {
                u64 a = dup2(STGm[(sbase + r) * 25 + m]);
                acc[r][0] = ffma2(a, bv0, acc[r][0]);
                acc[r][1] = ffma2(a, bv1, acc[r][1]);
            }
        }
        #pragma unroll
        for (int r = 0; r < 8; r++) {
            float2 f0 = unpk(acc[r][0]), f1 = unpk(acc[r][1]);
            *reinterpret_cast<float4*>(BA + (rowbase + r) * LDA + tx * 4) =
                make_float4(f0.x, f0.y, f1.x, f1.y);
        }
    }
    __syncthreads();

    // ---------- g1 = silu(g @ W1): M128 K64 N128 ----------
    {
        u64 acc[8][4] = {};
        gemm_acc<4>(BA, LDA, 64, 0, BW, 128, tx, rowbase, acc);
        #pragma unroll
        for (int r = 0; r < 8; r++) {
            float2 f0 = unpk(acc[r][0]), f1 = unpk(acc[r][1]);
            float2 f2 = unpk(acc[r][2]), f3 = unpk(acc[r][3]);
            f0.x = silu_f(f0.x); f0.y = silu_f(f0.y);
            f1.x = silu_f(f1.x); f1.y = silu_f(f1.y);
            f2.x = silu_f(f2.x); f2.y = silu_f(f2.y);
            f3.x = silu_f(f3.x); f3.y = silu_f(f3.y);
            float* dst = BB + (rowbase + r) * LDB + tx * 8;
            *reinterpret_cast<float4*>(dst)     = make_float4(f0.x, f0.y, f1.x, f1.y);
            *reinterpret_cast<float4*>(dst + 4) = make_float4(f2.x, f2.y, f3.x, f3.y);
        }
    }
    __syncthreads();
    {   // stage W2 rows 0..63
        float4* d = (float4*)BW; const float4* s = (const float4*)gw2;
        #pragma unroll
        for (int i = tid; i < 2048; i += NTH) d[i] = s[i];
    }
    __syncthreads();

    // ---------- g2 = silu(g1 @ W2): M128 K128 N128 (two k-halves) ----------
    {
        u64 acc[8][4] = {};
        gemm_acc<4>(BB, LDB, 64, 0, BW, 128, tx, rowbase, acc);
        __syncthreads();
        {   // stage W2 rows 64..127
            float4* d = (float4*)BW; const float4* s = (const float4*)(gw2 + 8192);
            #pragma unroll
            for (int i = tid; i < 2048; i += NTH) d[i] = s[i];
        }
        __syncthreads();
        gemm_acc<4>(BB, LDB, 64, 64, BW, 128, tx, rowbase, acc);
        #pragma unroll
        for (int r = 0; r < 8; r++) {
            float2 f0 = unpk(acc[r][0]), f1 = unpk(acc[r][1]);
            float2 f2 = unpk(acc[r][2]), f3 = unpk(acc[r][3]);
            f0.x = silu_f(f0.x); f0.y = silu_f(f0.y);
            f1.x = silu_f(f1.x); f1.y = silu_f(f1.y);
            f2.x = silu_f(f2.x); f2.y = silu_f(f2.y);
            f3.x = silu_f(f3.x); f3.y = silu_f(f3.y);
            float* dst = BC + (rowbase + r) * LDB + tx * 8;
            *reinterpret_cast<float4*>(dst)     = make_float4(f0.x, f0.y, f1.x, f1.y);
            *reinterpret_cast<float4*>(dst + 4) = make_float4(f2.x, f2.y, f3.x, f3.y);
        }
    }
    __syncthreads();
    {   // stage W3 full (128x64 = 8192 floats)
        float4* d = (float4*)BW; const float4* s = (const float4*)gw3;
        #pragma unroll
        for (int i = tid; i < 2048; i += NTH) d[i] = s[i];
    }
    __syncthreads();

    // ---------- g3 = g2 @ W3: M128 K128 N64 -> bufA ----------
    {
        u64 acc[8][2] = {};
        gemm_acc<2>(BC, LDB, 128, 0, BW, 64, tx, rowbase, acc);
        #pragma unroll
        for (int r = 0; r < 8; r++) {
            float2 f0 = unpk(acc[r][0]), f1 = unpk(acc[r][1]);
            *reinterpret_cast<float4*>(BA + (rowbase + r) * LDA + tx * 4) =
                make_float4(f0.x, f0.y, f1.x, f1.y);
        }
    }
    __syncthreads();

    // ---------- from_grid: hb[m,c] = sum_s tg[s,m] g3[s,c], m=1..24; row0=gating ----------
    {
        const int j2 = t & 31, grp = t >> 5;   // rows 1+grp+4s, s<6
        float* hb_h = HBUF + half * 1600;
        u64 acc[6] = {};
        for (int s = 0; s < 64; s++) {
            u64 gv = *reinterpret_cast<const u64*>(BA + (half * 64 + s) * LDA + j2 * 2);
            #pragma unroll
            for (int r = 0; r < 6; r++)
                acc[r] = ffma2(dup2(STGm[s * 25 + 1 + grp + 4 * r]), gv, acc[r]);
        }
        #pragma unroll
        for (int r = 0; r < 6; r++)
            *reinterpret_cast<float2*>(hb_h + (1 + grp + 4 * r) * 64 + j2 * 2) = unpk(acc[r]);
        if (t < 64) hb_h[t] = SGAT[half * 64 + t];
    }
    __syncthreads();

    // ---------- lin2: out = hb @ lin2_w[deg] (+b row0) ----------
    {
        const int j2 = t & 31, grp = t >> 5;
        const float* hb_h = HBUF + half * 1600;
        float* outn = out + (n2 * 2 + half) * 1600;
        for (int l = 0; l < 5; l++) {
            const int base = l * l, cnt = 2 * l + 1;
            const int r0 = base + grp, r1 = r0 + 4, r2 = r1 + 4;
            const bool b0 = grp < cnt, b1 = grp + 4 < cnt, b2 = grp + 8 < cnt;
            u64 a0 = 0, a1 = 0, a2 = 0;
            const float* w = l2w + l * 4096 + j2 * 2;
            #pragma unroll 4
            for (int i = 0; i < 64; i++) {
                u64 wv = *reinterpret_cast<const u64*>(w + i * 64);
                if (b0) a0 = ffma2(dup2(hb_h[r0 * 64 + i]), wv, a0);
                if (b1) a1 = ffma2(dup2(hb_h[r1 * 64 + i]), wv, a1);
                if (b2) a2 = ffma2(dup2(hb_h[r2 * 64 + i]), wv, a2);
            }
            if (b0) {
                float2 f = unpk(a0);
                if (r0 == 0) { f.x += l2b[j2 * 2]; f.y += l2b[j2 * 2 + 1]; }
                *reinterpret_cast<float2*>(outn + r0 * 64 + j2 * 2) = f;
            }
            if (b1) *reinterpret_cast<float2*>(outn + r1 * 64 + j2 * 2) = unpk(a1);
            if (b2) *reinterpret_cast<float2*>(outn + r2 * 64 + j2 * 2) = unpk(a2);
        }
    }
}

extern "C" void kernel_launch(void* const* d_in, const int* in_sizes, int n_in,
                              void* d_out, int out_size)
{
    const float* x    = (const float*)d_in[0];
    const float* nl0w = (const float*)d_in[1];
    const float* nl0b = (const float*)d_in[2];
    const float* affw = (const float*)d_in[3];
    const float* l1w  = (const float*)d_in[4];
    const float* l1b  = (const float*)d_in[5];
    const float* scw  = (const float*)d_in[6];
    const float* scb  = (const float*)d_in[7];
    const float* gw1  = (const float*)d_in[8];
    const float* gw2  = (const float*)d_in[9];
    const float* gw3  = (const float*)d_in[10];
    const float* l2w  = (const float*)d_in[11];
    const float* l2b  = (const float*)d_in[12];
    const float* tg   = (const float*)d_in[13];
    float* out = (float*)d_out;

    const int N = in_sizes[0] / 1600;
    const int NPAIR = N / 2;
    const size_t smem = SMEM_FLOATS * sizeof(float);

    cudaFuncSetAttribute(fused_equi, cudaFuncAttributeMaxDynamicSharedMemorySize, (int)smem);
    fused_equi<<<NPAIR, NTH, smem>>>(x, nl0w, nl0b, affw, l1w, l1b, scw, scb,
                                     gw1, gw2, gw3, l2w, l2b, tg, out);
}

// round 7
// speedup vs baseline: 1.3994x; 1.3994x over previous
#include <cuda_runtime.h>
#include <math.h>

typedef unsigned long long u64;

// N=20000 fixed. Scratch (sanctioned __device__ globals):
__device__ float g_buf[81920000];    // g (N,64,64); reused for g3
__device__ float g1_buf[163840000];  // g1 (N,64,128)
__device__ float g2_buf[163840000];  // g2 (N,64,128)
__device__ float gat_buf[1280000];   // gating (N,64)

__device__ __constant__ int c_deg[25] = {
    0, 1,1,1, 2,2,2,2,2, 3,3,3,3,3,3,3, 4,4,4,4,4,4,4,4,4
};
__device__ __constant__ float c_bw[25] = {
    0.f,
    1.f/12.f, 1.f/12.f, 1.f/12.f,
    1.f/20.f, 1.f/20.f, 1.f/20.f, 1.f/20.f, 1.f/20.f,
    1.f/28.f, 1.f/28.f, 1.f/28.f, 1.f/28.f, 1.f/28.f, 1.f/28.f, 1.f/28.f,
    1.f/36.f, 1.f/36.f, 1.f/36.f, 1.f/36.f, 1.f/36.f, 1.f/36.f, 1.f/36.f, 1.f/36.f, 1.f/36.f
};

__device__ __forceinline__ u64 ffma2(u64 a, u64 b, u64 c) {
    u64 d;
    asm("fma.rn.f32x2 %0, %1, %2, %3;" : "=l"(d) : "l"(a), "l"(b), "l"(c));
    return d;
}
__device__ __forceinline__ u64 dup2(float x) {
    u64 r; asm("mov.b64 %0, {%1, %1};" : "=l"(r) : "f"(x)); return r;
}
__device__ __forceinline__ float2 unpk(u64 v) {
    float2 f; asm("mov.b64 {%0, %1}, %2;" : "=f"(f.x), "=f"(f.y) : "l"(v)); return f;
}
__device__ __forceinline__ float silu_f(float v) {
    return v * (1.f / (1.f + __expf(-v)));
}

// ================== batched MLP GEMM body ==================
// A: [blocks*128, KT*64], W: [KT*64, NOUT], O: [blocks*128, NOUT]
#define LDA 66
template<int KT, int NOUT, bool SILU>
__device__ __forceinline__ void gemm_body(const float* __restrict__ A,
                                          const float* __restrict__ W,
                                          float* __restrict__ O)
{
    constexpr int K = KT * 64;
    constexpr int NQ = NOUT / 32;          // f32x2 accs per row (4 or 2)
    extern __shared__ float smf[];
    float* sA = smf;                       // 128 x LDA
    float* sW = smf + 128 * LDA;           // 64 x NOUT (one K-chunk)

    const int tid = threadIdx.x;
    const long long blk = blockIdx.x;
    const float* Ab = A + blk * (128LL * K);
    const int ty = tid >> 4, tx = tid & 15;
    const int rowbase = ty * 8;

    u64 acc[8][NQ] = {};
    for (int kt = 0; kt < KT; kt++) {
        // stage A chunk (128 x 64) as float2 (LDA=66 keeps float2 alignment)
        for (int i = tid; i < 4096; i += 256) {
            int row = i >> 5, c2 = i & 31;
            float2 v = *reinterpret_cast<const float2*>(Ab + (long long)row * K + kt * 64 + c2 * 2);
            *reinterpret_cast<float2*>(sA + row * LDA + c2 * 2) = v;
        }
        // stage W chunk (64 x NOUT)
        for (int i = tid; i < 64 * NOUT / 4; i += 256)
            reinterpret_cast<float4*>(sW)[i] =
                reinterpret_cast<const float4*>(W + kt * 64 * NOUT)[i];
        __syncthreads();

        #pragma unroll 8
        for (int k = 0; k < 64; k++) {
            u64 b[NQ];
            #pragma unroll
            for (int q = 0; q < NQ; q += 2) {
                ulonglong2 bw = *reinterpret_cast<const ulonglong2*>(
                    sW + k * NOUT + tx * (NQ * 2) + q * 2);
                b[q] = bw.x; b[q + 1] = bw.y;
            }
            #pragma unroll
            for (int r = 0; r < 8; r++) {
                u64 a = dup2(sA[(rowbase + r) * LDA + k]);
                #pragma unroll
                for (int q = 0; q < NQ; q++)
                    acc[r][q] = ffma2(a, b[q], acc[r][q]);
            }
        }
        __syncthreads();
    }

    float* Ob = O + blk * (128LL * NOUT);
    #pragma unroll
    for (int r = 0; r < 8; r++) {
        #pragma unroll
        for (int q = 0; q < NQ; q += 2) {
            float2 f0 = unpk(acc[r][q]), f1 = unpk(acc[r][q + 1]);
            if (SILU) {
                f0.x = silu_f(f0.x); f0.y = silu_f(f0.y);
                f1.x = silu_f(f1.x); f1.y = silu_f(f1.y);
            }
            *reinterpret_cast<float4*>(Ob + (long long)(rowbase + r) * NOUT + tx * (NQ * 2) + q * 2)
                = make_float4(f0.x, f0.y, f1.x, f1.y);
        }
    }
}

__global__ __launch_bounds__(256, 2) void k_g1(const float* __restrict__ W) {
    gemm_body<1, 128, true>(g_buf, W, g1_buf);
}
__global__ __launch_bounds__(256, 2) void k_g2(const float* __restrict__ W) {
    gemm_body<2, 128, true>(g1_buf, W, g2_buf);
}
__global__ __launch_bounds__(256, 2) void k_g3(const float* __restrict__ W) {
    gemm_body<2, 64, false>(g2_buf, W, g_buf);   // g3 aliases g (g dead after k_g1)
}

// ================== front: norm + gating + lin1 + to_grid ==================
__global__ __launch_bounds__(256)
void k_front(const float* __restrict__ x,
             const float* __restrict__ nl0w, const float* __restrict__ nl0b,
             const float* __restrict__ affw,
             const float* __restrict__ l1w, const float* __restrict__ l1b,
             const float* __restrict__ scw, const float* __restrict__ scb,
             const float* __restrict__ tg)
{
    __shared__ float smf[8192];
    float* SXN = smf;          // 3200 (2 samples)
    float* SH  = smf + 3200;   // 3200
    float* STG = smf + 6400;   // 1600
    float* RED = smf + 8000;   // 64

    const int tid = threadIdx.x;
    const int half = tid >> 7, t = tid & 127;
    const long long n2 = blockIdx.x;

    const float* xin = x + n2 * 3200;
    for (int i = tid; i < 3200; i += 256) SXN[i] = xin[i];
    for (int i = tid; i < 1600; i += 256) STG[i] = tg[i];
    __syncthreads();

    float* sxn_h = SXN + half * 1600;
    float* sh_h  = SH  + half * 1600;

    // stats per half
    {
        float s0 = 0.f, q0 = 0.f, fn = 0.f;
        for (int i = t; i < 1600; i += 128) {
            float v = sxn_h[i];
            int m = i >> 6;
            if (m == 0) { s0 += v; q0 += v * v; }
            else        { fn += c_bw[m] * v * v; }
        }
        #pragma unroll
        for (int off = 16; off > 0; off >>= 1) {
            s0 += __shfl_xor_sync(0xffffffffu, s0, off);
            q0 += __shfl_xor_sync(0xffffffffu, q0, off);
            fn += __shfl_xor_sync(0xffffffffu, fn, off);
        }
        int hw = (tid >> 5) & 3, lane = tid & 31;
        if (lane == 0) {
            RED[half * 32 + hw]      = s0;
            RED[half * 32 + 8 + hw]  = q0;
            RED[half * 32 + 16 + hw] = fn;
        }
        __syncthreads();
        if (t == 0) {
            float a = 0.f, b = 0.f, c = 0.f;
            #pragma unroll
            for (int w = 0; w < 4; w++) {
                a += RED[half * 32 + w];
                b += RED[half * 32 + 8 + w];
                c += RED[half * 32 + 16 + w];
            }
            float mu  = a * (1.f / 64.f);
            float var = b * (1.f / 64.f) - mu * mu;
            RED[half * 32 + 24] = mu;
            RED[half * 32 + 25] = rsqrtf(var + 1e-5f);
            RED[half * 32 + 26] = rsqrtf(c * (1.f / 64.f) + 1e-5f);
        }
        __syncthreads();
    }
    const float mu   = RED[half * 32 + 24];
    const float rstd = RED[half * 32 + 25];
    const float inv  = RED[half * 32 + 26];

    for (int i = t; i < 1600; i += 128) {
        int m = i >> 6, cc = i & 63;
        float v = sxn_h[i];
        if (m == 0) v = (v - mu) * rstd * nl0w[cc] + nl0b[cc];
        else        v = v * inv * affw[(c_deg[m] - 1) * 64 + cc];
        sxn_h[i] = v;
    }
    __syncthreads();

    // gating -> gmem
    if (t < 64) {
        float acc = scb[t];
        #pragma unroll 8
        for (int i = 0; i < 64; i++) acc += sxn_h[i] * scw[i * 64 + t];
        gat_buf[(n2 * 2 + half) * 64 + t] = silu_f(acc);
    }

    // lin1 (proven f32x2 form)
    {
        const int j2 = t & 31, grp = t >> 5;
        for (int l = 0; l < 5; l++) {
            const int base = l * l, cnt = 2 * l + 1;
            const int r0 = base + grp, r1 = r0 + 4, r2 = r1 + 4;
            const bool b0 = grp < cnt, b1 = grp + 4 < cnt, b2 = grp + 8 < cnt;
            u64 a0 = 0, a1 = 0, a2 = 0;
            const float* w = l1w + l * 4096 + j2 * 2;
            #pragma unroll 4
            for (int i = 0; i < 64; i++) {
                u64 wv = *reinterpret_cast<const u64*>(w + i * 64);
                if (b0) a0 = ffma2(dup2(sxn_h[r0 * 64 + i]), wv, a0);
                if (b1) a1 = ffma2(dup2(sxn_h[r1 * 64 + i]), wv, a1);
                if (b2) a2 = ffma2(dup2(sxn_h[r2 * 64 + i]), wv, a2);
            }
            if (b0) {
                float2 f = unpk(a0);
                if (r0 == 0) { f.x += l1b[j2 * 2]; f.y += l1b[j2 * 2 + 1]; }
                *reinterpret_cast<float2*>(sh_h + r0 * 64 + j2 * 2) = f;
            }
            if (b1) *reinterpret_cast<float2*>(sh_h + r1 * 64 + j2 * 2) = unpk(a1);
            if (b2) *reinterpret_cast<float2*>(sh_h + r2 * 64 + j2 * 2) = unpk(a2);
        }
    }
    __syncthreads();

    // to_grid -> g_buf (global rows n2*128 + row)
    {
        const int ty = tid >> 4, tx = tid & 15;
        const int rowbase = ty * 8;
        const float* shh = SH + (ty >= 8 ? 1600 : 0);
        const int sbase = (ty & 7) * 8;
        u64 acc[8][2] = {};
        for (int m = 0; m < 25; m++) {
            u64 bv0 = *reinterpret_cast<const u64*>(shh + m * 64 + tx * 4);
            u64 bv1 = *reinterpret_cast<const u64*>(shh + m * 64 + tx * 4 + 2);
            #pragma unroll
            for (int r = 0; r < 8; r++) {
                u64 a = dup2(STG[(sbase + r) * 25 + m]);
                acc[r][0] = ffma2(a, bv0, acc[r][0]);
                acc[r][1] = ffma2(a, bv1, acc[r][1]);
            }
        }
        #pragma unroll
        for (int r = 0; r < 8; r++) {
            float2 f0 = unpk(acc[r][0]), f1 = unpk(acc[r][1]);
            *reinterpret_cast<float4*>(g_buf + (n2 * 128 + rowbase + r) * 64 + tx * 4)
                = make_float4(f0.x, f0.y, f1.x, f1.y);
        }
    }
}

// ================== back: from_grid + lin2 ==================
__global__ __launch_bounds__(256)
void k_back(const float* __restrict__ l2w, const float* __restrict__ l2b,
            const float* __restrict__ tg, float* __restrict__ out)
{
    extern __shared__ float smf[];
    float* SG3 = smf;            // 128 x 66 = 8448
    float* HB  = smf + 8448;     // 3200
    float* STG = smf + 11648;    // 1600

    const int tid = threadIdx.x;
    const int half = tid >> 7, t = tid & 127;
    const long long n2 = blockIdx.x;

    for (int i = tid; i < 4096; i += 256) {
        int row = i >> 5, c2 = i & 31;
        float2 v = *reinterpret_cast<const float2*>(g_buf + (n2 * 128 + row) * 64 + c2 * 2);
        *reinterpret_cast<float2*>(SG3 + row * 66 + c2 * 2) = v;
    }
    for (int i = tid; i < 1600; i += 256) STG[i] = tg[i];
    __syncthreads();

    // from_grid (proven form)
    {
        const int j2 = t & 31, grp = t >> 5;   // rows 1+grp+4r, r<6
        float* hb_h = HB + half * 1600;
        u64 acc[6] = {};
        for (int s = 0; s < 64; s++) {
            u64 gv = *reinterpret_cast<const u64*>(SG3 + (half * 64 + s) * 66 + j2 * 2);
            #pragma unroll
            for (int r = 0; r < 6; r++)
                acc[r] = ffma2(dup2(STG[s * 25 + 1 + grp + 4 * r]), gv, acc[r]);
        }
        #pragma unroll
        for (int r = 0; r < 6; r++)
            *reinterpret_cast<float2*>(hb_h + (1 + grp + 4 * r) * 64 + j2 * 2) = unpk(acc[r]);
        if (t < 64) hb_h[t] = gat_buf[(n2 * 2 + half) * 64 + t];
    }
    __syncthreads();

    // lin2 (proven form)
    {
        const int j2 = t & 31, grp = t >> 5;
        const float* hb_h = HB + half * 1600;
        float* outn = out + (n2 * 2 + half) * 1600;
        for (int l = 0; l < 5; l++) {
            const int base = l * l, cnt = 2 * l + 1;
            const int r0 = base + grp, r1 = r0 + 4, r2 = r1 + 4;
            const bool b0 = grp < cnt, b1 = grp + 4 < cnt, b2 = grp + 8 < cnt;
            u64 a0 = 0, a1 = 0, a2 = 0;
            const float* w = l2w + l * 4096 + j2 * 2;
            #pragma unroll 4
            for (int i = 0; i < 64; i++) {
                u64 wv = *reinterpret_cast<const u64*>(w + i * 64);
                if (b0) a0 = ffma2(dup2(hb_h[r0 * 64 + i]), wv, a0);
                if (b1) a1 = ffma2(dup2(hb_h[r1 * 64 + i]), wv, a1);
                if (b2) a2 = ffma2(dup2(hb_h[r2 * 64 + i]), wv, a2);
            }
            if (b0) {
                float2 f = unpk(a0);
                if (r0 == 0) { f.x += l2b[j2 * 2]; f.y += l2b[j2 * 2 + 1]; }
                *reinterpret_cast<float2*>(outn + r0 * 64 + j2 * 2) = f;
            }
            if (b1) *reinterpret_cast<float2*>(outn + r1 * 64 + j2 * 2) = unpk(a1);
            if (b2) *reinterpret_cast<float2*>(outn + r2 * 64 + j2 * 2) = unpk(a2);
        }
    }
}

extern "C" void kernel_launch(void* const* d_in, const int* in_sizes, int n_in,
                              void* d_out, int out_size)
{
    const float* x    = (const float*)d_in[0];
    const float* nl0w = (const float*)d_in[1];
    const float* nl0b = (const float*)d_in[2];
    const float* affw = (const float*)d_in[3];
    const float* l1w  = (const float*)d_in[4];
    const float* l1b  = (const float*)d_in[5];
    const float* scw  = (const float*)d_in[6];
    const float* scb  = (const float*)d_in[7];
    const float* gw1  = (const float*)d_in[8];
    const float* gw2  = (const float*)d_in[9];
    const float* gw3  = (const float*)d_in[10];
    const float* l2w  = (const float*)d_in[11];
    const float* l2b  = (const float*)d_in[12];
    const float* tg   = (const float*)d_in[13];
    float* out = (float*)d_out;

    const int N = in_sizes[0] / 1600;
    const int NPAIR = N / 2;   // also the 128-row GEMM block count

    const int smem_g1 = (128 * LDA + 64 * 128) * 4;   // 66560
    const int smem_g3 = (128 * LDA + 64 * 64) * 4;    // 50176
    const int smem_bk = (8448 + 3200 + 1600) * 4;     // 52992

    cudaFuncSetAttribute(k_g1, cudaFuncAttributeMaxDynamicSharedMemorySize, smem_g1);
    cudaFuncSetAttribute(k_g2, cudaFuncAttributeMaxDynamicSharedMemorySize, smem_g1);
    cudaFuncSetAttribute(k_g3, cudaFuncAttributeMaxDynamicSharedMemorySize, smem_g3);
    cudaFuncSetAttribute(k_back, cudaFuncAttributeMaxDynamicSharedMemorySize, smem_bk);

    k_front<<<NPAIR, 256>>>(x, nl0w, nl0b, affw, l1w, l1b, scw, scb, tg);
    k_g1<<<NPAIR, 256, smem_g1>>>(gw1);
    k_g2<<<NPAIR, 256, smem_g1>>>(gw2);
    k_g3<<<NPAIR, 256, smem_g3>>>(gw3);
    k_back<<<NPAIR, 256, smem_bk>>>(l2w, l2b, tg, out);
}

// round 8
// speedup vs baseline: 1.4207x; 1.0152x over previous
#include <cuda_runtime.h>
#include <math.h>

typedef unsigned long long u64;

// Scratch (N=20000): g1 (N*64*128), g2 (N*64*128), gating (N*64)
__device__ __align__(16) float g1_buf[163840000];
__device__ __align__(16) float g2_buf[163840000];
__device__ __align__(16) float gat_buf[1280000];

__device__ __constant__ int c_deg[25] = {
    0, 1,1,1, 2,2,2,2,2, 3,3,3,3,3,3,3, 4,4,4,4,4,4,4,4,4
};
__device__ __constant__ float c_bw[25] = {
    0.f,
    1.f/12.f, 1.f/12.f, 1.f/12.f,
    1.f/20.f, 1.f/20.f, 1.f/20.f, 1.f/20.f, 1.f/20.f,
    1.f/28.f, 1.f/28.f, 1.f/28.f, 1.f/28.f, 1.f/28.f, 1.f/28.f, 1.f/28.f,
    1.f/36.f, 1.f/36.f, 1.f/36.f, 1.f/36.f, 1.f/36.f, 1.f/36.f, 1.f/36.f, 1.f/36.f, 1.f/36.f
};

__device__ __forceinline__ u64 ffma2(u64 a, u64 b, u64 c) {
    u64 d;
    asm("fma.rn.f32x2 %0, %1, %2, %3;" : "=l"(d) : "l"(a), "l"(b), "l"(c));
    return d;
}
__device__ __forceinline__ u64 dup2(float x) {
    u64 r; asm("mov.b64 %0, {%1, %1};" : "=l"(r) : "f"(x)); return r;
}
__device__ __forceinline__ float2 unpk(u64 v) {
    float2 f; asm("mov.b64 {%0, %1}, %2;" : "=f"(f.x), "=f"(f.y) : "l"(v)); return f;
}
__device__ __forceinline__ float silu_f(float v) {
    return v * (1.f / (1.f + __expf(-v)));
}

#define LDA 68   // smem A-tile stride (float4-aligned, conflict-benign)

// 64-k-chunk GEMM accumulate. sA: 128 x LDA smem, sW: 64 x ldw smem.
// Thread (ty,tx) of (16,16): rows ty*8..+8, cols tx*(NQ*2)*... (NQ u64 col-pairs).
template<int NQ>
__device__ __forceinline__ void gemm_chunk(const float* __restrict__ sA,
                                           const float* __restrict__ sW, int ldw,
                                           int tx, int rowbase, u64 acc[8][NQ])
{
    #pragma unroll 2
    for (int k0 = 0; k0 < 64; k0 += 4) {
        float4 av[8];
        #pragma unroll
        for (int r = 0; r < 8; r++)
            av[r] = *reinterpret_cast<const float4*>(sA + (rowbase + r) * LDA + k0);
        #pragma unroll
        for (int kk = 0; kk < 4; kk++) {
            u64 b[NQ];
            #pragma unroll
            for (int q = 0; q < NQ; q += 2) {
                ulonglong2 bw = *reinterpret_cast<const ulonglong2*>(
                    sW + (k0 + kk) * ldw + tx * (NQ * 2) + q * 2);
                b[q] = bw.x; b[q + 1] = bw.y;
            }
            #pragma unroll
            for (int r = 0; r < 8; r++) {
                const float* ap = reinterpret_cast<const float*>(&av[r]);
                u64 a = dup2(ap[kk]);
                #pragma unroll
                for (int q = 0; q < NQ; q++)
                    acc[r][q] = ffma2(a, b[q], acc[r][q]);
            }
        }
    }
}

// ============ kernel 1: norm + gating + lin1 + to_grid + g1-GEMM ============
// smem: SXN 3200 | SH 3200 | STG 1600 | RED 64 | SG 128*68=8704 | SW 8192 = 24960 fl
#define SM1_FLOATS 24960
__global__ __launch_bounds__(256, 2)
void k_front_g1(const float* __restrict__ x,
                const float* __restrict__ nl0w, const float* __restrict__ nl0b,
                const float* __restrict__ affw,
                const float* __restrict__ l1w, const float* __restrict__ l1b,
                const float* __restrict__ scw, const float* __restrict__ scb,
                const float* __restrict__ gw1, const float* __restrict__ tg)
{
    extern __shared__ float smf[];
    float* SXN = smf;           // 3200
    float* SH  = smf + 3200;    // 3200
    float* STG = smf + 6400;    // 1600
    float* RED = smf + 8000;    // 64
    float* SG  = smf + 8064;    // 8704
    float* SW  = smf + 16768;   // 8192

    const int tid = threadIdx.x;
    const int half = tid >> 7, t = tid & 127;
    const long long n2 = blockIdx.x;

    const float* xin = x + n2 * 3200;
    for (int i = tid; i < 3200; i += 256) SXN[i] = xin[i];
    for (int i = tid; i < 1600; i += 256) STG[i] = tg[i];
    for (int i = tid; i < 2048; i += 256)
        reinterpret_cast<float4*>(SW)[i] = reinterpret_cast<const float4*>(gw1)[i];
    __syncthreads();

    float* sxn_h = SXN + half * 1600;
    float* sh_h  = SH  + half * 1600;

    // stats per half
    {
        float s0 = 0.f, q0 = 0.f, fn = 0.f;
        for (int i = t; i < 1600; i += 128) {
            float v = sxn_h[i];
            int m = i >> 6;
            if (m == 0) { s0 += v; q0 += v * v; }
            else        { fn += c_bw[m] * v * v; }
        }
        #pragma unroll
        for (int off = 16; off > 0; off >>= 1) {
            s0 += __shfl_xor_sync(0xffffffffu, s0, off);
            q0 += __shfl_xor_sync(0xffffffffu, q0, off);
            fn += __shfl_xor_sync(0xffffffffu, fn, off);
        }
        int hw = (tid >> 5) & 3, lane = tid & 31;
        if (lane == 0) {
            RED[half * 32 + hw]      = s0;
            RED[half * 32 + 8 + hw]  = q0;
            RED[half * 32 + 16 + hw] = fn;
        }
        __syncthreads();
        if (t == 0) {
            float a = 0.f, b = 0.f, c = 0.f;
            #pragma unroll
            for (int w = 0; w < 4; w++) {
                a += RED[half * 32 + w];
                b += RED[half * 32 + 8 + w];
                c += RED[half * 32 + 16 + w];
            }
            float mu  = a * (1.f / 64.f);
            float var = b * (1.f / 64.f) - mu * mu;
            RED[half * 32 + 24] = mu;
            RED[half * 32 + 25] = rsqrtf(var + 1e-5f);
            RED[half * 32 + 26] = rsqrtf(c * (1.f / 64.f) + 1e-5f);
        }
        __syncthreads();
    }
    const float mu   = RED[half * 32 + 24];
    const float rstd = RED[half * 32 + 25];
    const float inv  = RED[half * 32 + 26];

    for (int i = t; i < 1600; i += 128) {
        int m = i >> 6, cc = i & 63;
        float v = sxn_h[i];
        if (m == 0) v = (v - mu) * rstd * nl0w[cc] + nl0b[cc];
        else        v = v * inv * affw[(c_deg[m] - 1) * 64 + cc];
        sxn_h[i] = v;
    }
    __syncthreads();

    // gating -> gmem
    if (t < 64) {
        float acc = scb[t];
        #pragma unroll 8
        for (int i = 0; i < 64; i++) acc += sxn_h[i] * scw[i * 64 + t];
        gat_buf[(n2 * 2 + half) * 64 + t] = silu_f(acc);
    }

    // lin1
    {
        const int j2 = t & 31, grp = t >> 5;
        for (int l = 0; l < 5; l++) {
            const int base = l * l, cnt = 2 * l + 1;
            const int r0 = base + grp, r1 = r0 + 4, r2 = r1 + 4;
            const bool b0 = grp < cnt, b1 = grp + 4 < cnt, b2 = grp + 8 < cnt;
            u64 a0 = 0, a1 = 0, a2 = 0;
            const float* w = l1w + l * 4096 + j2 * 2;
            #pragma unroll 4
            for (int i = 0; i < 64; i++) {
                u64 wv = *reinterpret_cast<const u64*>(w + i * 64);
                if (b0) a0 = ffma2(dup2(sxn_h[r0 * 64 + i]), wv, a0);
                if (b1) a1 = ffma2(dup2(sxn_h[r1 * 64 + i]), wv, a1);
                if (b2) a2 = ffma2(dup2(sxn_h[r2 * 64 + i]), wv, a2);
            }
            if (b0) {
                float2 f = unpk(a0);
                if (r0 == 0) { f.x += l1b[j2 * 2]; f.y += l1b[j2 * 2 + 1]; }
                *reinterpret_cast<float2*>(sh_h + r0 * 64 + j2 * 2) = f;
            }
            if (b1) *reinterpret_cast<float2*>(sh_h + r1 * 64 + j2 * 2) = unpk(a1);
            if (b2) *reinterpret_cast<float2*>(sh_h + r2 * 64 + j2 * 2) = unpk(a2);
        }
    }
    __syncthreads();

    const int ty = tid >> 4, tx = tid & 15;
    const int rowbase = ty * 8;

    // to_grid -> SG (smem, LDA stride)
    {
        const float* shh = SH + (ty >= 8 ? 1600 : 0);
        const int sbase = (ty & 7) * 8;
        u64 acc[8][2] = {};
        for (int m = 0; m < 25; m++) {
            u64 bv0 = *reinterpret_cast<const u64*>(shh + m * 64 + tx * 4);
            u64 bv1 = *reinterpret_cast<const u64*>(shh + m * 64 + tx * 4 + 2);
            #pragma unroll
            for (int r = 0; r < 8; r++) {
                u64 a = dup2(STG[(sbase + r) * 25 + m]);
                acc[r][0] = ffma2(a, bv0, acc[r][0]);
                acc[r][1] = ffma2(a, bv1, acc[r][1]);
            }
        }
        #pragma unroll
        for (int r = 0; r < 8; r++) {
            float2 f0 = unpk(acc[r][0]), f1 = unpk(acc[r][1]);
            *reinterpret_cast<float4*>(SG + (rowbase + r) * LDA + tx * 4) =
                make_float4(f0.x, f0.y, f1.x, f1.y);
        }
    }
    __syncthreads();

    // g1 = silu(g @ W1): K=64, N=128 -> g1_buf
    {
        u64 acc[8][4] = {};
        gemm_chunk<4>(SG, SW, 128, tx, rowbase, acc);
        float* Ob = g1_buf + n2 * (128LL * 128);
        #pragma unroll
        for (int r = 0; r < 8; r++) {
            #pragma unroll
            for (int q = 0; q < 4; q += 2) {
                float2 f0 = unpk(acc[r][q]), f1 = unpk(acc[r][q + 1]);
                f0.x = silu_f(f0.x); f0.y = silu_f(f0.y);
                f1.x = silu_f(f1.x); f1.y = silu_f(f1.y);
                *reinterpret_cast<float4*>(Ob + (long long)(rowbase + r) * 128 + tx * 8 + q * 2)
                    = make_float4(f0.x, f0.y, f1.x, f1.y);
            }
        }
    }
}

// ============ kernel 2: g2 = silu(g1 @ W2), K=128 N=128 ============
#define SM2_FLOATS (128 * LDA + 64 * 128)   // 16896
__global__ __launch_bounds__(256, 2)
void k_g2(const float* __restrict__ W)
{
    extern __shared__ float smf[];
    float* sA = smf;               // 128 x LDA
    float* sW = smf + 128 * LDA;   // 64 x 128

    const int tid = threadIdx.x;
    const long long blk = blockIdx.x;
    const int ty = tid >> 4, tx = tid & 15;
    const int rowbase = ty * 8;
    const float* Ab = g1_buf + blk * (128LL * 128);

    u64 acc[8][4] = {};
    #pragma unroll
    for (int kt = 0; kt < 2; kt++) {
        for (int i = tid; i < 2048; i += 256) {
            int row = i >> 4, c4 = i & 15;
            *reinterpret_cast<float4*>(sA + row * LDA + c4 * 4) =
                *reinterpret_cast<const float4*>(Ab + (long long)row * 128 + kt * 64 + c4 * 4);
        }
        for (int i = tid; i < 2048; i += 256)
            reinterpret_cast<float4*>(sW)[i] =
                reinterpret_cast<const float4*>(W + kt * 8192)[i];
        __syncthreads();
        gemm_chunk<4>(sA, sW, 128, tx, rowbase, acc);
        __syncthreads();
    }

    float* Ob = g2_buf + blk * (128LL * 128);
    #pragma unroll
    for (int r = 0; r < 8; r++) {
        #pragma unroll
        for (int q = 0; q < 4; q += 2) {
            float2 f0 = unpk(acc[r][q]), f1 = unpk(acc[r][q + 1]);
            f0.x = silu_f(f0.x); f0.y = silu_f(f0.y);
            f1.x = silu_f(f1.x); f1.y = silu_f(f1.y);
            *reinterpret_cast<float4*>(Ob + (long long)(rowbase + r) * 128 + tx * 8 + q * 2)
                = make_float4(f0.x, f0.y, f1.x, f1.y);
        }
    }
}

// ============ kernel 3: g3-GEMM + from_grid + lin2 ============
// smem: sA 8704 | sW 4096 | SG3 8704 | HB 3200 | STG 1600 = 26304 fl
#define SM3_FLOATS 26304
__global__ __launch_bounds__(256, 2)
void k_g3_back(const float* __restrict__ W3,
               const float* __restrict__ l2w, const float* __restrict__ l2b,
               const float* __restrict__ tg, float* __restrict__ out)
{
    extern __shared__ float smf[];
    float* sA  = smf;            // 128 x LDA
    float* sW  = smf + 8704;     // 64 x 64
    float* SG3 = smf + 12800;    // 128 x LDA
    float* HB  = smf + 21504;    // 3200
    float* STG = smf + 24704;    // 1600

    const int tid = threadIdx.x;
    const int half = tid >> 7, t = tid & 127;
    const long long n2 = blockIdx.x;
    const int ty = tid >> 4, tx = tid & 15;
    const int rowbase = ty * 8;
    const float* Ab = g2_buf + n2 * (128LL * 128);

    for (int i = tid; i < 1600; i += 256) STG[i] = tg[i];

    // g3 = g2 @ W3 (K=128, N=64) -> SG3
    u64 acc[8][2] = {};
    #pragma unroll
    for (int kt = 0; kt < 2; kt++) {
        for (int i = tid; i < 2048; i += 256) {
            int row = i >> 4, c4 = i & 15;
            *reinterpret_cast<float4*>(sA + row * LDA + c4 * 4) =
                *reinterpret_cast<const float4*>(Ab + (long long)row * 128 + kt * 64 + c4 * 4);
        }
        for (int i = tid; i < 1024; i += 256)
            reinterpret_cast<float4*>(sW)[i] =
                reinterpret_cast<const float4*>(W3 + kt * 4096)[i];
        __syncthreads();
        gemm_chunk<2>(sA, sW, 64, tx, rowbase, acc);
        __syncthreads();
    }
    #pragma unroll
    for (int r = 0; r < 8; r++) {
        float2 f0 = unpk(acc[r][0]), f1 = unpk(acc[r][1]);
        *reinterpret_cast<float4*>(SG3 + (rowbase + r) * LDA + tx * 4) =
            make_float4(f0.x, f0.y, f1.x, f1.y);
    }
    __syncthreads();

    // from_grid: hb[m] = sum_s tg[s,m] g3[s], m=1..24; row0 = gating
    {
        const int j2 = t & 31, grp = t >> 5;
        float* hb_h = HB + half * 1600;
        u64 a6[6] = {};
        for (int s = 0; s < 64; s++) {
            u64 gv = *reinterpret_cast<const u64*>(SG3 + (half * 64 + s) * LDA + j2 * 2);
            #pragma unroll
            for (int r = 0; r < 6; r++)
                a6[r] = ffma2(dup2(STG[s * 25 + 1 + grp + 4 * r]), gv, a6[r]);
        }
        #pragma unroll
        for (int r = 0; r < 6; r++)
            *reinterpret_cast<float2*>(hb_h + (1 + grp + 4 * r) * 64 + j2 * 2) = unpk(a6[r]);
        if (t < 64) hb_h[t] = gat_buf[(n2 * 2 + half) * 64 + t];
    }
    __syncthreads();

    // lin2
    {
        const int j2 = t & 31, grp = t >> 5;
        const float* hb_h = HB + half * 1600;
        float* outn = out + (n2 * 2 + half) * 1600;
        for (int l = 0; l < 5; l++) {
            const int base = l * l, cnt = 2 * l + 1;
            const int r0 = base + grp, r1 = r0 + 4, r2 = r1 + 4;
            const bool b0 = grp < cnt, b1 = grp + 4 < cnt, b2 = grp + 8 < cnt;
            u64 a0 = 0, a1 = 0, a2 = 0;
            const float* w = l2w + l * 4096 + j2 * 2;
            #pragma unroll 4
            for (int i = 0; i < 64; i++) {
                u64 wv = *reinterpret_cast<const u64*>(w + i * 64);
                if (b0) a0 = ffma2(dup2(hb_h[r0 * 64 + i]), wv, a0);
                if (b1) a1 = ffma2(dup2(hb_h[r1 * 64 + i]), wv, a1);
                if (b2) a2 = ffma2(dup2(hb_h[r2 * 64 + i]), wv, a2);
            }
            if (b0) {
                float2 f = unpk(a0);
                if (r0 == 0) { f.x += l2b[j2 * 2]; f.y += l2b[j2 * 2 + 1]; }
                *reinterpret_cast<float2*>(outn + r0 * 64 + j2 * 2) = f;
            }
            if (b1) *reinterpret_cast<float2*>(outn + r1 * 64 + j2 * 2) = unpk(a1);
            if (b2) *reinterpret_cast<float2*>(outn + r2 * 64 + j2 * 2) = unpk(a2);
        }
    }
}

extern "C" void kernel_launch(void* const* d_in, const int* in_sizes, int n_in,
                              void* d_out, int out_size)
{
    const float* x    = (const float*)d_in[0];
    const float* nl0w = (const float*)d_in[1];
    const float* nl0b = (const float*)d_in[2];
    const float* affw = (const float*)d_in[3];
    const float* l1w  = (const float*)d_in[4];
    const float* l1b  = (const float*)d_in[5];
    const float* scw  = (const float*)d_in[6];
    const float* scb  = (const float*)d_in[7];
    const float* gw1  = (const float*)d_in[8];
    const float* gw2  = (const float*)d_in[9];
    const float* gw3  = (const float*)d_in[10];
    const float* l2w  = (const float*)d_in[11];
    const float* l2b  = (const float*)d_in[12];
    const float* tg   = (const float*)d_in[13];
    float* out = (float*)d_out;

    const int N = in_sizes[0] / 1600;
    const int NPAIR = N / 2;

    const int sm1 = SM1_FLOATS * 4;
    const int sm2 = SM2_FLOATS * 4;
    const int sm3 = SM3_FLOATS * 4;

    cudaFuncSetAttribute(k_front_g1, cudaFuncAttributeMaxDynamicSharedMemorySize, sm1);
    cudaFuncSetAttribute(k_g2,       cudaFuncAttributeMaxDynamicSharedMemorySize, sm2);
    cudaFuncSetAttribute(k_g3_back,  cudaFuncAttributeMaxDynamicSharedMemorySize, sm3);

    k_front_g1<<<NPAIR, 256, sm1>>>(x, nl0w, nl0b, affw, l1w, l1b, scw, scb, gw1, tg);
    k_g2<<<NPAIR, 256, sm2>>>(gw2);
    k_g3_back<<<NPAIR, 256, sm3>>>(gw3, l2w, l2b, tg, out);
}

// round 9
// speedup vs baseline: 1.5527x; 1.0929x over previous
#include <cuda_runtime.h>
#include <math.h>

typedef unsigned long long u64;
typedef unsigned int u32;

// Scratch: g1/g2 as packed bf16 pairs (u32 = 2 halves). N=20000.
__device__ __align__(16) u32 g1_buf[81920000];   // N*64*128 bf16
__device__ __align__(16) u32 g2_buf[81920000];   // N*64*128 bf16
__device__ float gat_buf[1280000];               // N*64 gating

__device__ __constant__ int c_deg[25] = {
    0, 1,1,1, 2,2,2,2,2, 3,3,3,3,3,3,3, 4,4,4,4,4,4,4,4,4
};
__device__ __constant__ float c_bw[25] = {
    0.f,
    1.f/12.f, 1.f/12.f, 1.f/12.f,
    1.f/20.f, 1.f/20.f, 1.f/20.f, 1.f/20.f, 1.f/20.f,
    1.f/28.f, 1.f/28.f, 1.f/28.f, 1.f/28.f, 1.f/28.f, 1.f/28.f, 1.f/28.f,
    1.f/36.f, 1.f/36.f, 1.f/36.f, 1.f/36.f, 1.f/36.f, 1.f/36.f, 1.f/36.f, 1.f/36.f, 1.f/36.f
};

__device__ __forceinline__ u64 ffma2(u64 a, u64 b, u64 c) {
    u64 d;
    asm("fma.rn.f32x2 %0, %1, %2, %3;" : "=l"(d) : "l"(a), "l"(b), "l"(c));
    return d;
}
__device__ __forceinline__ u64 dup2(float x) {
    u64 r; asm("mov.b64 %0, {%1, %1};" : "=l"(r) : "f"(x)); return r;
}
__device__ __forceinline__ float2 unpk(u64 v) {
    float2 f; asm("mov.b64 {%0, %1}, %2;" : "=f"(f.x), "=f"(f.y) : "l"(v)); return f;
}
__device__ __forceinline__ float silu_f(float v) {
    return v * (1.f / (1.f + __expf(-v)));
}
// bf16x2 pack/unpack (hi = first PTX operand)
__device__ __forceinline__ u32 bpack(float lo, float hi) {
    u32 d; asm("cvt.rn.bf16x2.f32 %0, %1, %2;" : "=r"(d) : "f"(hi), "f"(lo)); return d;
}
__device__ __forceinline__ float blo(u32 p) { return __uint_as_float(p << 16); }
__device__ __forceinline__ float bhi(u32 p) { return __uint_as_float(p & 0xFFFF0000u); }

#define LDA 68

// 64-k GEMM chunk. sA: 128 x LDA, sW: 64 x ldw. (16,16) threads, 8 rows x NQ colpairs.
template<int NQ>
__device__ __forceinline__ void gemm_chunk(const float* __restrict__ sA,
                                           const float* __restrict__ sW, int ldw,
                                           int tx, int rowbase, u64 acc[8][NQ])
{
    #pragma unroll 2
    for (int k0 = 0; k0 < 64; k0 += 4) {
        float4 av[8];
        #pragma unroll
        for (int r = 0; r < 8; r++)
            av[r] = *reinterpret_cast<const float4*>(sA + (rowbase + r) * LDA + k0);
        #pragma unroll
        for (int kk = 0; kk < 4; kk++) {
            u64 b[NQ];
            #pragma unroll
            for (int q = 0; q < NQ; q += 2) {
                ulonglong2 bw = *reinterpret_cast<const ulonglong2*>(
                    sW + (k0 + kk) * ldw + tx * (NQ * 2) + q * 2);
                b[q] = bw.x; b[q + 1] = bw.y;
            }
            #pragma unroll
            for (int r = 0; r < 8; r++) {
                const float* ap = reinterpret_cast<const float*>(&av[r]);
                u64 a = dup2(ap[kk]);
                #pragma unroll
                for (int q = 0; q < NQ; q++)
                    acc[r][q] = ffma2(a, b[q], acc[r][q]);
            }
        }
    }
}

// stage bf16 A chunk (128 x 64 halves) -> sA fp32
__device__ __forceinline__ void stage_A_bf16(const u32* __restrict__ Ab, int kt, float* sA, int tid)
{
    for (int i = tid; i < 1024; i += 256) {
        int row = i >> 3, c4 = i & 7;
        uint4 v = *reinterpret_cast<const uint4*>(Ab + row * 64 + kt * 32 + c4 * 4);
        float* d = sA + row * LDA + c4 * 8;
        *reinterpret_cast<float4*>(d)     = make_float4(blo(v.x), bhi(v.x), blo(v.y), bhi(v.y));
        *reinterpret_cast<float4*>(d + 4) = make_float4(blo(v.z), bhi(v.z), blo(v.w), bhi(v.w));
    }
}

// ============ kernel 1: norm + gating + lin1(smem W) + to_grid + g1 ============
// smem fl: SXN 3200 | SH 3200 | STG 1600 | RED 64 | SG 8704 | SW 8192 = 24960
#define SM1_FLOATS 24960
__global__ __launch_bounds__(256, 2)
void k_front_g1(const float* __restrict__ x,
                const float* __restrict__ nl0w, const float* __restrict__ nl0b,
                const float* __restrict__ affw,
                const float* __restrict__ l1w, const float* __restrict__ l1b,
                const float* __restrict__ scw, const float* __restrict__ scb,
                const float* __restrict__ gw1, const float* __restrict__ tg)
{
    extern __shared__ float smf[];
    float* SXN = smf;           // 3200
    float* SH  = smf + 3200;    // 3200
    float* STG = smf + 6400;    // 1600
    float* RED = smf + 8000;    // 64
    float* SG  = smf + 8064;    // 8704 (weights stage, then g)
    float* SW  = smf + 16768;   // 8192 (gw1)

    const int tid = threadIdx.x;
    const int half = tid >> 7, t = tid & 127;
    const long long n2 = blockIdx.x;

    const float* xin = x + n2 * 3200;
    for (int i = tid; i < 3200; i += 256) SXN[i] = xin[i];
    for (int i = tid; i < 1600; i += 256) STG[i] = tg[i];
    for (int i = tid; i < 2048; i += 256)
        reinterpret_cast<float4*>(SW)[i] = reinterpret_cast<const float4*>(gw1)[i];
    for (int i = tid; i < 2048; i += 256)   // l1w degrees 0,1
        reinterpret_cast<float4*>(SG)[i] = reinterpret_cast<const float4*>(l1w)[i];
    __syncthreads();

    float* sxn_h = SXN + half * 1600;
    float* sh_h  = SH  + half * 1600;

    // stats
    {
        float s0 = 0.f, q0 = 0.f, fn = 0.f;
        for (int i = t; i < 1600; i += 128) {
            float v = sxn_h[i];
            int m = i >> 6;
            if (m == 0) { s0 += v; q0 += v * v; }
            else        { fn += c_bw[m] * v * v; }
        }
        #pragma unroll
        for (int off = 16; off > 0; off >>= 1) {
            s0 += __shfl_xor_sync(0xffffffffu, s0, off);
            q0 += __shfl_xor_sync(0xffffffffu, q0, off);
            fn += __shfl_xor_sync(0xffffffffu, fn, off);
        }
        int hw = (tid >> 5) & 3, lane = tid & 31;
        if (lane == 0) {
            RED[half * 32 + hw]      = s0;
            RED[half * 32 + 8 + hw]  = q0;
            RED[half * 32 + 16 + hw] = fn;
        }
        __syncthreads();
        if (t == 0) {
            float a = 0.f, b = 0.f, c = 0.f;
            #pragma unroll
            for (int w = 0; w < 4; w++) {
                a += RED[half * 32 + w];
                b += RED[half * 32 + 8 + w];
                c += RED[half * 32 + 16 + w];
            }
            float mu  = a * (1.f / 64.f);
            float var = b * (1.f / 64.f) - mu * mu;
            RED[half * 32 + 24] = mu;
            RED[half * 32 + 25] = rsqrtf(var + 1e-5f);
            RED[half * 32 + 26] = rsqrtf(c * (1.f / 64.f) + 1e-5f);
        }
        __syncthreads();
    }
    const float mu   = RED[half * 32 + 24];
    const float rstd = RED[half * 32 + 25];
    const float inv  = RED[half * 32 + 26];

    for (int i = t; i < 1600; i += 128) {
        int m = i >> 6, cc = i & 63;
        float v = sxn_h[i];
        if (m == 0) v = (v - mu) * rstd * nl0w[cc] + nl0b[cc];
        else        v = v * inv * affw[(c_deg[m] - 1) * 64 + cc];
        sxn_h[i] = v;
    }
    __syncthreads();

    if (t < 64) {
        float acc = scb[t];
        #pragma unroll 8
        for (int i = 0; i < 64; i++) acc += sxn_h[i] * scw[i * 64 + t];
        gat_buf[(n2 * 2 + half) * 64 + t] = silu_f(acc);
    }

    // lin1 with smem weights, degree pieces {0,1},{2,3},{4}
    {
        const int j2 = t & 31, grp = t >> 5;
        #pragma unroll
        for (int piece = 0; piece < 3; piece++) {
            const int d0 = piece * 2;
            const int nl = (piece == 2) ? 1 : 2;
            if (piece > 0) {
                __syncthreads();   // previous lin1 reads done
                for (int i = tid; i < nl * 1024; i += 256)
                    reinterpret_cast<float4*>(SG)[i] =
                        reinterpret_cast<const float4*>(l1w + d0 * 4096)[i];
                __syncthreads();
            }
            for (int li = 0; li < nl; li++) {
                const int l = d0 + li;
                const int base = l * l, cnt = 2 * l + 1;
                const int r0 = base + grp, r1 = r0 + 4, r2 = r1 + 4;
                const bool b0 = grp < cnt, b1 = grp + 4 < cnt, b2 = grp + 8 < cnt;
                u64 a0 = 0, a1 = 0, a2 = 0;
                const float* w = SG + li * 4096 + j2 * 2;
                #pragma unroll 4
                for (int i = 0; i < 64; i++) {
                    u64 wv = *reinterpret_cast<const u64*>(w + i * 64);
                    if (b0) a0 = ffma2(dup2(sxn_h[r0 * 64 + i]), wv, a0);
                    if (b1) a1 = ffma2(dup2(sxn_h[r1 * 64 + i]), wv, a1);
                    if (b2) a2 = ffma2(dup2(sxn_h[r2 * 64 + i]), wv, a2);
                }
                if (b0) {
                    float2 f = unpk(a0);
                    if (r0 == 0) { f.x += l1b[j2 * 2]; f.y += l1b[j2 * 2 + 1]; }
                    *reinterpret_cast<float2*>(sh_h + r0 * 64 + j2 * 2) = f;
                }
                if (b1) *reinterpret_cast<float2*>(sh_h + r1 * 64 + j2 * 2) = unpk(a1);
                if (b2) *reinterpret_cast<float2*>(sh_h + r2 * 64 + j2 * 2) = unpk(a2);
            }
        }
    }
    __syncthreads();

    const int ty = tid >> 4, tx = tid & 15;
    const int rowbase = ty * 8;

    // to_grid -> SG
    {
        const float* shh = SH + (ty >= 8 ? 1600 : 0);
        const int sbase = (ty & 7) * 8;
        u64 acc[8][2] = {};
        for (int m = 0; m < 25; m++) {
            u64 bv0 = *reinterpret_cast<const u64*>(shh + m * 64 + tx * 4);
            u64 bv1 = *reinterpret_cast<const u64*>(shh + m * 64 + tx * 4 + 2);
            #pragma unroll
            for (int r = 0; r < 8; r++) {
                u64 a = dup2(STG[(sbase + r) * 25 + m]);
                acc[r][0] = ffma2(a, bv0, acc[r][0]);
                acc[r][1] = ffma2(a, bv1, acc[r][1]);
            }
        }
        #pragma unroll
        for (int r = 0; r < 8; r++) {
            float2 f0 = unpk(acc[r][0]), f1 = unpk(acc[r][1]);
            *reinterpret_cast<float4*>(SG + (rowbase + r) * LDA + tx * 4) =
                make_float4(f0.x, f0.y, f1.x, f1.y);
        }
    }
    __syncthreads();

    // g1 = silu(g @ W1) -> g1_buf (bf16)
    {
        u64 acc[8][4] = {};
        gemm_chunk<4>(SG, SW, 128, tx, rowbase, acc);
        u32* Ob = g1_buf + n2 * (128LL * 64);
        #pragma unroll
        for (int r = 0; r < 8; r++) {
            float2 f0 = unpk(acc[r][0]), f1 = unpk(acc[r][1]);
            float2 f2 = unpk(acc[r][2]), f3 = unpk(acc[r][3]);
            u32 p0 = bpack(silu_f(f0.x), silu_f(f0.y));
            u32 p1 = bpack(silu_f(f1.x), silu_f(f1.y));
            u32 p2 = bpack(silu_f(f2.x), silu_f(f2.y));
            u32 p3 = bpack(silu_f(f3.x), silu_f(f3.y));
            *reinterpret_cast<uint4*>(Ob + (rowbase + r) * 64 + tx * 4) = make_uint4(p0, p1, p2, p3);
        }
    }
}

// ============ kernel 2: g2 = silu(g1 @ W2) (bf16 in/out) ============
#define SM2_FLOATS (128 * LDA + 128 * 128)   // 8704 + 16384 = 25088
__global__ __launch_bounds__(256, 2)
void k_g2(const float* __restrict__ W)
{
    extern __shared__ float smf[];
    float* sA = smf;             // 128 x LDA
    float* sW = smf + 8704;      // 128 x 128 (full W2)

    const int tid = threadIdx.x;
    const long long blk = blockIdx.x;
    const int ty = tid >> 4, tx = tid & 15;
    const int rowbase = ty * 8;
    const u32* Ab = g1_buf + blk * (128LL * 64);

    for (int i = tid; i < 4096; i += 256)
        reinterpret_cast<float4*>(sW)[i] = reinterpret_cast<const float4*>(W)[i];

    u64 acc[8][4] = {};
    #pragma unroll
    for (int kt = 0; kt < 2; kt++) {
        if (kt) __syncthreads();
        stage_A_bf16(Ab, kt, sA, tid);
        __syncthreads();
        gemm_chunk<4>(sA, sW + kt * 8192, 128, tx, rowbase, acc);
    }

    u32* Ob = g2_buf + blk * (128LL * 64);
    #pragma unroll
    for (int r = 0; r < 8; r++) {
        float2 f0 = unpk(acc[r][0]), f1 = unpk(acc[r][1]);
        float2 f2 = unpk(acc[r][2]), f3 = unpk(acc[r][3]);
        u32 p0 = bpack(silu_f(f0.x), silu_f(f0.y));
        u32 p1 = bpack(silu_f(f1.x), silu_f(f1.y));
        u32 p2 = bpack(silu_f(f2.x), silu_f(f2.y));
        u32 p3 = bpack(silu_f(f3.x), silu_f(f3.y));
        *reinterpret_cast<uint4*>(Ob + (rowbase + r) * 64 + tx * 4) = make_uint4(p0, p1, p2, p3);
    }
}

// ============ kernel 3: g3 + from_grid + lin2(smem W) ============
// smem fl: sA 8704 (then g3) | sW 8192 | HB 3200 | STG 1600 = 21696
#define SM3_FLOATS 21696
__global__ __launch_bounds__(256, 2)
void k_g3_back(const float* __restrict__ W3,
               const float* __restrict__ l2w, const float* __restrict__ l2b,
               const float* __restrict__ tg, float* __restrict__ out)
{
    extern __shared__ float smf[];
    float* sA  = smf;            // 128 x LDA; becomes SG3
    float* sW  = smf + 8704;     // 8192: W3 full, later l2w pieces
    float* HB  = smf + 16896;    // 3200
    float* STG = smf + 20096;    // 1600

    const int tid = threadIdx.x;
    const int half = tid >> 7, t = tid & 127;
    const long long n2 = blockIdx.x;
    const int ty = tid >> 4, tx = tid & 15;
    const int rowbase = ty * 8;
    const u32* Ab = g2_buf + n2 * (128LL * 64);

    for (int i = tid; i < 1600; i += 256) STG[i] = tg[i];
    for (int i = tid; i < 2048; i += 256)
        reinterpret_cast<float4*>(sW)[i] = reinterpret_cast<const float4*>(W3)[i];

    u64 acc[8][2] = {};
    #pragma unroll
    for (int kt = 0; kt < 2; kt++) {
        if (kt) __syncthreads();
        stage_A_bf16(Ab, kt, sA, tid);
        __syncthreads();
        gemm_chunk<2>(sA, sW + kt * 4096, 64, tx, rowbase, acc);
    }
    __syncthreads();   // all reads of sA done; now write g3 into it
    #pragma unroll
    for (int r = 0; r < 8; r++) {
        float2 f0 = unpk(acc[r][0]), f1 = unpk(acc[r][1]);
        *reinterpret_cast<float4*>(sA + (rowbase + r) * LDA + tx * 4) =
            make_float4(f0.x, f0.y, f1.x, f1.y);
    }
    __syncthreads();

    // from_grid -> HB, and stage l2w degrees {0,1} into sW
    {
        const int j2 = t & 31, grp = t >> 5;
        float* hb_h = HB + half * 1600;
        u64 a6[6] = {};
        for (int s = 0; s < 64; s++) {
            u64 gv = *reinterpret_cast<const u64*>(sA + (half * 64 + s) * LDA + j2 * 2);
            #pragma unroll
            for (int r = 0; r < 6; r++)
                a6[r] = ffma2(dup2(STG[s * 25 + 1 + grp + 4 * r]), gv, a6[r]);
        }
        #pragma unroll
        for (int r = 0; r < 6; r++)
            *reinterpret_cast<float2*>(hb_h + (1 + grp + 4 * r) * 64 + j2 * 2) = unpk(a6[r]);
        if (t < 64) hb_h[t] = gat_buf[(n2 * 2 + half) * 64 + t];
    }
    for (int i = tid; i < 2048; i += 256)
        reinterpret_cast<float4*>(sW)[i] = reinterpret_cast<const float4*>(l2w)[i];
    __syncthreads();

    // lin2 with smem weights, pieces {0,1},{2,3},{4}
    {
        const int j2 = t & 31, grp = t >> 5;
        const float* hb_h = HB + half * 1600;
        float* outn = out + (n2 * 2 + half) * 1600;
        #pragma unroll
        for (int piece = 0; piece < 3; piece++) {
            const int d0 = piece * 2;
            const int nl = (piece == 2) ? 1 : 2;
            if (piece > 0) {
                __syncthreads();
                for (int i = tid; i < nl * 1024; i += 256)
                    reinterpret_cast<float4*>(sW)[i] =
                        reinterpret_cast<const float4*>(l2w + d0 * 4096)[i];
                __syncthreads();
            }
            for (int li = 0; li < nl; li++) {
                const int l = d0 + li;
                const int base = l * l, cnt = 2 * l + 1;
                const int r0 = base + grp, r1 = r0 + 4, r2 = r1 + 4;
                const bool b0 = grp < cnt, b1 = grp + 4 < cnt, b2 = grp + 8 < cnt;
                u64 a0 = 0, a1 = 0, a2 = 0;
                const float* w = sW + li * 4096 + j2 * 2;
                #pragma unroll 4
                for (int i = 0; i < 64; i++) {
                    u64 wv = *reinterpret_cast<const u64*>(w + i * 64);
                    if (b0) a0 = ffma2(dup2(hb_h[r0 * 64 + i]), wv, a0);
                    if (b1) a1 = ffma2(dup2(hb_h[r1 * 64 + i]), wv, a1);
                    if (b2) a2 = ffma2(dup2(hb_h[r2 * 64 + i]), wv, a2);
                }
                if (b0) {
                    float2 f = unpk(a0);
                    if (r0 == 0) { f.x += l2b[j2 * 2]; f.y += l2b[j2 * 2 + 1]; }
                    *reinterpret_cast<float2*>(outn + r0 * 64 + j2 * 2) = f;
                }
                if (b1) *reinterpret_cast<float2*>(outn + r1 * 64 + j2 * 2) = unpk(a1);
                if (b2) *reinterpret_cast<float2*>(outn + r2 * 64 + j2 * 2) = unpk(a2);
            }
        }
    }
}

extern "C" void kernel_launch(void* const* d_in, const int* in_sizes, int n_in,
                              void* d_out, int out_size)
{
    const float* x    = (const float*)d_in[0];
    const float* nl0w = (const float*)d_in[1];
    const float* nl0b = (const float*)d_in[2];
    const float* affw = (const float*)d_in[3];
    const float* l1w  = (const float*)d_in[4];
    const float* l1b  = (const float*)d_in[5];
    const float* scw  = (const float*)d_in[6];
    const float* scb  = (const float*)d_in[7];
    const float* gw1  = (const float*)d_in[8];
    const float* gw2  = (const float*)d_in[9];
    const float* gw3  = (const float*)d_in[10];
    const float* l2w  = (const float*)d_in[11];
    const float* l2b  = (const float*)d_in[12];
    const float* tg   = (const float*)d_in[13];
    float* out = (float*)d_out;

    const int N = in_sizes[0] / 1600;
    const int NPAIR = N / 2;

    cudaFuncSetAttribute(k_front_g1, cudaFuncAttributeMaxDynamicSharedMemorySize, SM1_FLOATS * 4);
    cudaFuncSetAttribute(k_g2,       cudaFuncAttributeMaxDynamicSharedMemorySize, SM2_FLOATS * 4);
    cudaFuncSetAttribute(k_g3_back,  cudaFuncAttributeMaxDynamicSharedMemorySize, SM3_FLOATS * 4);

    k_front_g1<<<NPAIR, 256, SM1_FLOATS * 4>>>(x, nl0w, nl0b, affw, l1w, l1b, scw, scb, gw1, tg);
    k_g2<<<NPAIR, 256, SM2_FLOATS * 4>>>(gw2);
    k_g3_back<<<NPAIR, 256, SM3_FLOATS * 4>>>(gw3, l2w, l2b, tg, out);
}

// round 10
// speedup vs baseline: 1.6726x; 1.0772x over previous
#include <cuda_runtime.h>
#include <math.h>

typedef unsigned long long u64;
typedef unsigned int u32;

// Scratch: N=20000
__device__ __align__(16) float h_buf[32000000];   // h (N,25,64) fp32
__device__ __align__(16) u32 g1_buf[81920000];    // g1 (N,64,128) bf16
__device__ __align__(16) u32 g2_buf[81920000];    // g2 (N,64,128) bf16
__device__ float gat_buf[1280000];                // gating (N,64)

__device__ __constant__ int c_deg[25] = {
    0, 1,1,1, 2,2,2,2,2, 3,3,3,3,3,3,3, 4,4,4,4,4,4,4,4,4
};
__device__ __constant__ float c_bw[25] = {
    0.f,
    1.f/12.f, 1.f/12.f, 1.f/12.f,
    1.f/20.f, 1.f/20.f, 1.f/20.f, 1.f/20.f, 1.f/20.f,
    1.f/28.f, 1.f/28.f, 1.f/28.f, 1.f/28.f, 1.f/28.f, 1.f/28.f, 1.f/28.f,
    1.f/36.f, 1.f/36.f, 1.f/36.f, 1.f/36.f, 1.f/36.f, 1.f/36.f, 1.f/36.f, 1.f/36.f, 1.f/36.f
};

__device__ __forceinline__ u64 ffma2(u64 a, u64 b, u64 c) {
    u64 d;
    asm("fma.rn.f32x2 %0, %1, %2, %3;" : "=l"(d) : "l"(a), "l"(b), "l"(c));
    return d;
}
__device__ __forceinline__ u64 dup2(float x) {
    u64 r; asm("mov.b64 %0, {%1, %1};" : "=l"(r) : "f"(x)); return r;
}
__device__ __forceinline__ float2 unpk(u64 v) {
    float2 f; asm("mov.b64 {%0, %1}, %2;" : "=f"(f.x), "=f"(f.y) : "l"(v)); return f;
}
__device__ __forceinline__ float silu_f(float v) {
    return v * (1.f / (1.f + __expf(-v)));
}
__device__ __forceinline__ u32 bpack(float lo, float hi) {
    u32 d; asm("cvt.rn.bf16x2.f32 %0, %1, %2;" : "=r"(d) : "f"(hi), "f"(lo)); return d;
}
__device__ __forceinline__ float blo(u32 p) { return __uint_as_float(p << 16); }
__device__ __forceinline__ float bhi(u32 p) { return __uint_as_float(p & 0xFFFF0000u); }

#define LDA  68   // k_g1 A-tile stride
#define LDA2 36   // 32-k chunk A-tile stride

// GEMM chunk: sA 128 x LDAX, sW KC x ldw. (16,16) threads, 8 rows x NQ u64 col-pairs.
template<int NQ, int KC, int LDAX>
__device__ __forceinline__ void gemm_chunk(const float* __restrict__ sA,
                                           const float* __restrict__ sW, int ldw,
                                           int tx, int rowbase, u64 acc[8][NQ])
{
    #pragma unroll 2
    for (int k0 = 0; k0 < KC; k0 += 4) {
        float4 av[8];
        #pragma unroll
        for (int r = 0; r < 8; r++)
            av[r] = *reinterpret_cast<const float4*>(sA + (rowbase + r) * LDAX + k0);
        #pragma unroll
        for (int kk = 0; kk < 4; kk++) {
            u64 b[NQ];
            #pragma unroll
            for (int q = 0; q < NQ; q += 2) {
                ulonglong2 bw = *reinterpret_cast<const ulonglong2*>(
                    sW + (k0 + kk) * ldw + tx * (NQ * 2) + q * 2);
                b[q] = bw.x; b[q + 1] = bw.y;
            }
            #pragma unroll
            for (int r = 0; r < 8; r++) {
                const float* ap = reinterpret_cast<const float*>(&av[r]);
                u64 a = dup2(ap[kk]);
                #pragma unroll
                for (int q = 0; q < NQ; q++)
                    acc[r][q] = ffma2(a, b[q], acc[r][q]);
            }
        }
    }
}

__device__ __forceinline__ void sts8(float* d, uint4 v) {
    *reinterpret_cast<float4*>(d)     = make_float4(blo(v.x), bhi(v.x), blo(v.y), bhi(v.y));
    *reinterpret_cast<float4*>(d + 4) = make_float4(blo(v.z), bhi(v.z), blo(v.w), bhi(v.w));
}

// ============ kernel 1: norm + gating + lin1 -> h_buf (high occupancy) ============
__global__ __launch_bounds__(256, 4)
void k_norm(const float* __restrict__ x,
            const float* __restrict__ nl0w, const float* __restrict__ nl0b,
            const float* __restrict__ affw,
            const float* __restrict__ l1w, const float* __restrict__ l1b,
            const float* __restrict__ scw, const float* __restrict__ scb)
{
    __shared__ float SXN[3200];
    __shared__ float RED[64];

    const int tid = threadIdx.x;
    const int half = tid >> 7, t = tid & 127;
    const long long n2 = blockIdx.x;

    const float4* xin = reinterpret_cast<const float4*>(x + n2 * 3200);
    for (int i = tid; i < 800; i += 256)
        reinterpret_cast<float4*>(SXN)[i] = xin[i];
    __syncthreads();

    float* sxn_h = SXN + half * 1600;

    // stats
    {
        float s0 = 0.f, q0 = 0.f, fn = 0.f;
        for (int i = t; i < 1600; i += 128) {
            float v = sxn_h[i];
            int m = i >> 6;
            if (m == 0) { s0 += v; q0 += v * v; }
            else        { fn += c_bw[m] * v * v; }
        }
        #pragma unroll
        for (int off = 16; off > 0; off >>= 1) {
            s0 += __shfl_xor_sync(0xffffffffu, s0, off);
            q0 += __shfl_xor_sync(0xffffffffu, q0, off);
            fn += __shfl_xor_sync(0xffffffffu, fn, off);
        }
        int hw = (tid >> 5) & 3, lane = tid & 31;
        if (lane == 0) {
            RED[half * 32 + hw]      = s0;
            RED[half * 32 + 8 + hw]  = q0;
            RED[half * 32 + 16 + hw] = fn;
        }
        __syncthreads();
        if (t == 0) {
            float a = 0.f, b = 0.f, c = 0.f;
            #pragma unroll
            for (int w = 0; w < 4; w++) {
                a += RED[half * 32 + w];
                b += RED[half * 32 + 8 + w];
                c += RED[half * 32 + 16 + w];
            }
            float mu  = a * (1.f / 64.f);
            float var = b * (1.f / 64.f) - mu * mu;
            RED[half * 32 + 24] = mu;
            RED[half * 32 + 25] = rsqrtf(var + 1e-5f);
            RED[half * 32 + 26] = rsqrtf(c * (1.f / 64.f) + 1e-5f);
        }
        __syncthreads();
    }
    const float mu   = RED[half * 32 + 24];
    const float rstd = RED[half * 32 + 25];
    const float inv  = RED[half * 32 + 26];

    for (int i = t; i < 1600; i += 128) {
        int m = i >> 6, cc = i & 63;
        float v = sxn_h[i];
        if (m == 0) v = (v - mu) * rstd * nl0w[cc] + nl0b[cc];
        else        v = v * inv * affw[(c_deg[m] - 1) * 64 + cc];
        sxn_h[i] = v;
    }
    __syncthreads();

    if (t < 64) {
        float acc = scb[t];
        #pragma unroll 8
        for (int i = 0; i < 64; i++) acc += sxn_h[i] * scw[i * 64 + t];
        gat_buf[(n2 * 2 + half) * 64 + t] = silu_f(acc);
    }

    // lin1 -> h_buf
    {
        const int j2 = t & 31, grp = t >> 5;
        float* hout = h_buf + (n2 * 2 + half) * 1600;
        for (int l = 0; l < 5; l++) {
            const int base = l * l, cnt = 2 * l + 1;
            const int r0 = base + grp, r1 = r0 + 4, r2 = r1 + 4;
            const bool b0 = grp < cnt, b1 = grp + 4 < cnt, b2 = grp + 8 < cnt;
            u64 a0 = 0, a1 = 0, a2 = 0;
            const float* w = l1w + l * 4096 + j2 * 2;
            #pragma unroll 4
            for (int i = 0; i < 64; i++) {
                u64 wv = *reinterpret_cast<const u64*>(w + i * 64);
                if (b0) a0 = ffma2(dup2(sxn_h[r0 * 64 + i]), wv, a0);
                if (b1) a1 = ffma2(dup2(sxn_h[r1 * 64 + i]), wv, a1);
                if (b2) a2 = ffma2(dup2(sxn_h[r2 * 64 + i]), wv, a2);
            }
            if (b0) {
                float2 f = unpk(a0);
                if (r0 == 0) { f.x += l1b[j2 * 2]; f.y += l1b[j2 * 2 + 1]; }
                *reinterpret_cast<float2*>(hout + r0 * 64 + j2 * 2) = f;
            }
            if (b1) *reinterpret_cast<float2*>(hout + r1 * 64 + j2 * 2) = unpk(a1);
            if (b2) *reinterpret_cast<float2*>(hout + r2 * 64 + j2 * 2) = unpk(a2);
        }
    }
}

// ============ kernel 2: to_grid + g1 GEMM ============
// smem fl: SH 3200 | STG 1600 | SG 8704 | SW 8192 = 21696
#define SM_G1 21696
__global__ __launch_bounds__(256, 2)
void k_g1(const float* __restrict__ gw1, const float* __restrict__ tg)
{
    extern __shared__ float smf[];
    float* SH  = smf;            // 3200
    float* STG = smf + 3200;     // 1600
    float* SG  = smf + 4800;     // 8704
    float* SW  = smf + 13504;    // 8192

    const int tid = threadIdx.x;
    const long long n2 = blockIdx.x;
    const int ty = tid >> 4, tx = tid & 15;
    const int rowbase = ty * 8;

    const float4* hin = reinterpret_cast<const float4*>(h_buf + n2 * 3200);
    for (int i = tid; i < 800; i += 256)
        reinterpret_cast<float4*>(SH)[i] = hin[i];
    for (int i = tid; i < 1600; i += 256) STG[i] = tg[i];
    for (int i = tid; i < 2048; i += 256)
        reinterpret_cast<float4*>(SW)[i] = reinterpret_cast<const float4*>(gw1)[i];
    __syncthreads();

    // to_grid -> SG
    {
        const float* shh = SH + (ty >= 8 ? 1600 : 0);
        const int sbase = (ty & 7) * 8;
        u64 acc[8][2] = {};
        for (int m = 0; m < 25; m++) {
            u64 bv0 = *reinterpret_cast<const u64*>(shh + m * 64 + tx * 4);
            u64 bv1 = *reinterpret_cast<const u64*>(shh + m * 64 + tx * 4 + 2);
            #pragma unroll
            for (int r = 0; r < 8; r++) {
                u64 a = dup2(STG[(sbase + r) * 25 + m]);
                acc[r][0] = ffma2(a, bv0, acc[r][0]);
                acc[r][1] = ffma2(a, bv1, acc[r][1]);
            }
        }
        #pragma unroll
        for (int r = 0; r < 8; r++) {
            float2 f0 = unpk(acc[r][0]), f1 = unpk(acc[r][1]);
            *reinterpret_cast<float4*>(SG + (rowbase + r) * LDA + tx * 4) =
                make_float4(f0.x, f0.y, f1.x, f1.y);
        }
    }
    __syncthreads();

    // g1 = silu(g @ W1) -> g1_buf bf16
    {
        u64 acc[8][4] = {};
        gemm_chunk<4, 64, LDA>(SG, SW, 128, tx, rowbase, acc);
        u32* Ob = g1_buf + n2 * (128LL * 64);
        #pragma unroll
        for (int r = 0; r < 8; r++) {
            float2 f0 = unpk(acc[r][0]), f1 = unpk(acc[r][1]);
            float2 f2 = unpk(acc[r][2]), f3 = unpk(acc[r][3]);
            u32 p0 = bpack(silu_f(f0.x), silu_f(f0.y));
            u32 p1 = bpack(silu_f(f1.x), silu_f(f1.y));
            u32 p2 = bpack(silu_f(f2.x), silu_f(f2.y));
            u32 p3 = bpack(silu_f(f3.x), silu_f(f3.y));
            *reinterpret_cast<uint4*>(Ob + (rowbase + r) * 64 + tx * 4) = make_uint4(p0, p1, p2, p3);
        }
    }
}

// ============ kernel 3: g2 = silu(g1 @ W2), double-buffered A ============
// smem fl: sA0 4608 | sA1 4608 | sW 16384 = 25600
#define SM_G2 25600
__global__ __launch_bounds__(256, 2)
void k_g2(const float* __restrict__ W)
{
    extern __shared__ float smf[];
    float* sA0 = smf;            // 128 x LDA2
    float* sA1 = smf + 4608;
    float* sW  = smf + 9216;     // 128 x 128

    const int tid = threadIdx.x;
    const long long blk = blockIdx.x;
    const int ty = tid >> 4, tx = tid & 15;
    const int rowbase = ty * 8;
    const u32* Ab = g1_buf + blk * (128LL * 64);

    const int r0i = tid >> 2, c0i = tid & 3;
    const int r1i = (tid + 256) >> 2, c1i = (tid + 256) & 3;

    for (int i = tid; i < 4096; i += 256)
        reinterpret_cast<float4*>(sW)[i] = reinterpret_cast<const float4*>(W)[i];

    uint4 va = *reinterpret_cast<const uint4*>(Ab + r0i * 64 + c0i * 4);
    uint4 vb = *reinterpret_cast<const uint4*>(Ab + r1i * 64 + c1i * 4);
    sts8(sA0 + r0i * LDA2 + c0i * 8, va);
    sts8(sA1 - 4608 + 4608 + r1i * LDA2 + c1i * 8 - 4608 + 4608, vb);  // plain sA0 second half
    // NOTE: both rows of chunk go to the SAME buffer:
    // (r1i covers rows 64..127)
    sts8(sA0 + r1i * LDA2 + c1i * 8, vb);
    __syncthreads();

    float* bufs[2] = { sA0, sA1 };
    u64 acc[8][4] = {};
    #pragma unroll
    for (int kt = 0; kt < 4; kt++) {
        uint4 na, nb;
        if (kt < 3) {
            na = *reinterpret_cast<const uint4*>(Ab + r0i * 64 + (kt + 1) * 16 + c0i * 4);
            nb = *reinterpret_cast<const uint4*>(Ab + r1i * 64 + (kt + 1) * 16 + c1i * 4);
        }
        gemm_chunk<4, 32, LDA2>(bufs[kt & 1], sW + kt * 32 * 128, 128, tx, rowbase, acc);
        if (kt < 3) {
            float* nbuf = bufs[(kt + 1) & 1];
            sts8(nbuf + r0i * LDA2 + c0i * 8, na);
            sts8(nbuf + r1i * LDA2 + c1i * 8, nb);
        }
        __syncthreads();
    }

    u32* Ob = g2_buf + blk * (128LL * 64);
    #pragma unroll
    for (int r = 0; r < 8; r++) {
        float2 f0 = unpk(acc[r][0]), f1 = unpk(acc[r][1]);
        float2 f2 = unpk(acc[r][2]), f3 = unpk(acc[r][3]);
        u32 p0 = bpack(silu_f(f0.x), silu_f(f0.y));
        u32 p1 = bpack(silu_f(f1.x), silu_f(f1.y));
        u32 p2 = bpack(silu_f(f2.x), silu_f(f2.y));
        u32 p3 = bpack(silu_f(f3.x), silu_f(f3.y));
        *reinterpret_cast<uint4*>(Ob + (rowbase + r) * 64 + tx * 4) = make_uint4(p0, p1, p2, p3);
    }
}

// ============ kernel 4: g3 GEMM (double-buffered) + from_grid + lin2 ============
// smem fl: sA0 4608 | sA1 4608 | sW 8192 | HB 3200 | STG 1600 = 22208
#define SM_G3 22208
__global__ __launch_bounds__(256, 2)
void k_g3_back(const float* __restrict__ W3,
               const float* __restrict__ l2w, const float* __restrict__ l2b,
               const float* __restrict__ tg, float* __restrict__ out)
{
    extern __shared__ float smf[];
    float* sA0 = smf;            // 128 x LDA2
    float* sA1 = smf + 4608;
    float* sW  = smf + 9216;     // 8192
    float* HB  = smf + 17408;    // 3200
    float* STG = smf + 20608;    // 1600
    float* SG3 = smf;            // aliases sA0/sA1 after GEMM (128 x LDA)

    const int tid = threadIdx.x;
    const int half = tid >> 7, t = tid & 127;
    const long long n2 = blockIdx.x;
    const int ty = tid >> 4, tx = tid & 15;
    const int rowbase = ty * 8;
    const u32* Ab = g2_buf + n2 * (128LL * 64);

    const int r0i = tid >> 2, c0i = tid & 3;
    const int r1i = (tid + 256) >> 2, c1i = (tid + 256) & 3;

    for (int i = tid; i < 1600; i += 256) STG[i] = tg[i];
    for (int i = tid; i < 2048; i += 256)
        reinterpret_cast<float4*>(sW)[i] = reinterpret_cast<const float4*>(W3)[i];

    {
        uint4 va = *reinterpret_cast<const uint4*>(Ab + r0i * 64 + c0i * 4);
        uint4 vb = *reinterpret_cast<const uint4*>(Ab + r1i * 64 + c1i * 4);
        sts8(sA0 + r0i * LDA2 + c0i * 8, va);
        sts8(sA0 + r1i * LDA2 + c1i * 8, vb);
    }
    __syncthreads();

    float* bufs[2] = { sA0, sA1 };
    u64 acc[8][2] = {};
    #pragma unroll
    for (int kt = 0; kt < 4; kt++) {
        uint4 na, nb;
        if (kt < 3) {
            na = *reinterpret_cast<const uint4*>(Ab + r0i * 64 + (kt + 1) * 16 + c0i * 4);
            nb = *reinterpret_cast<const uint4*>(Ab + r1i * 64 + (kt + 1) * 16 + c1i * 4);
        }
        gemm_chunk<2, 32, LDA2>(bufs[kt & 1], sW + kt * 32 * 64, 64, tx, rowbase, acc);
        if (kt < 3) {
            float* nbuf = bufs[(kt + 1) & 1];
            sts8(nbuf + r0i * LDA2 + c0i * 8, na);
            sts8(nbuf + r1i * LDA2 + c1i * 8, nb);
        }
        __syncthreads();
    }

    // write g3 into SG3 (aliases the A buffers; all reads complete)
    #pragma unroll
    for (int r = 0; r < 8; r++) {
        float2 f0 = unpk(acc[r][0]), f1 = unpk(acc[r][1]);
        *reinterpret_cast<float4*>(SG3 + (rowbase + r) * LDA + tx * 4) =
            make_float4(f0.x, f0.y, f1.x, f1.y);
    }
    __syncthreads();

    // from_grid -> HB; stage l2w {0,1} into sW (W3 dead)
    {
        const int j2 = t & 31, grp = t >> 5;
        float* hb_h = HB + half * 1600;
        u64 a6[6] = {};
        for (int s = 0; s < 64; s++) {
            u64 gv = *reinterpret_cast<const u64*>(SG3 + (half * 64 + s) * LDA + j2 * 2);
            #pragma unroll
            for (int r = 0; r < 6; r++)
                a6[r] = ffma2(dup2(STG[s * 25 + 1 + grp + 4 * r]), gv, a6[r]);
        }
        #pragma unroll
        for (int r = 0; r < 6; r++)
            *reinterpret_cast<float2*>(hb_h + (1 + grp + 4 * r) * 64 + j2 * 2) = unpk(a6[r]);
        if (t < 64) hb_h[t] = gat_buf[(n2 * 2 + half) * 64 + t];
    }
    for (int i = tid; i < 2048; i += 256)
        reinterpret_cast<float4*>(sW)[i] = reinterpret_cast<const float4*>(l2w)[i];
    __syncthreads();

    // lin2 (smem weights, pieces {0,1},{2,3},{4})
    {
        const int j2 = t & 31, grp = t >> 5;
        const float* hb_h = HB + half * 1600;
        float* outn = out + (n2 * 2 + half) * 1600;
        #pragma unroll
        for (int piece = 0; piece < 3; piece++) {
            const int d0 = piece * 2;
            const int nl = (piece == 2) ? 1 : 2;
            if (piece > 0) {
                __syncthreads();
                for (int i = tid; i < nl * 1024; i += 256)
                    reinterpret_cast<float4*>(sW)[i] =
                        reinterpret_cast<const float4*>(l2w + d0 * 4096)[i];
                __syncthreads();
            }
            for (int li = 0; li < nl; li++) {
                const int l = d0 + li;
                const int base = l * l, cnt = 2 * l + 1;
                const int r0 = base + grp, r1 = r0 + 4, r2 = r1 + 4;
                const bool b0 = grp < cnt, b1 = grp + 4 < cnt, b2 = grp + 8 < cnt;
                u64 a0 = 0, a1 = 0, a2 = 0;
                const float* w = sW + li * 4096 + j2 * 2;
                #pragma unroll 4
                for (int i = 0; i < 64; i++) {
                    u64 wv = *reinterpret_cast<const u64*>(w + i * 64);
                    if (b0) a0 = ffma2(dup2(hb_h[r0 * 64 + i]), wv, a0);
                    if (b1) a1 = ffma2(dup2(hb_h[r1 * 64 + i]), wv, a1);
                    if (b2) a2 = ffma2(dup2(hb_h[r2 * 64 + i]), wv, a2);
                }
                if (b0) {
                    float2 f = unpk(a0);
                    if (r0 == 0) { f.x += l2b[j2 * 2]; f.y += l2b[j2 * 2 + 1]; }
                    *reinterpret_cast<float2*>(outn + r0 * 64 + j2 * 2) = f;
                }
                if (b1) *reinterpret_cast<float2*>(outn + r1 * 64 + j2 * 2) = unpk(a1);
                if (b2) *reinterpret_cast<float2*>(outn + r2 * 64 + j2 * 2) = unpk(a2);
            }
        }
    }
}

extern "C" void kernel_launch(void* const* d_in, const int* in_sizes, int n_in,
                              void* d_out, int out_size)
{
    const float* x    = (const float*)d_in[0];
    const float* nl0w = (const float*)d_in[1];
    const float* nl0b = (const float*)d_in[2];
    const float* affw = (const float*)d_in[3];
    const float* l1w  = (const float*)d_in[4];
    const float* l1b  = (const float*)d_in[5];
    const float* scw  = (const float*)d_in[6];
    const float* scb  = (const float*)d_in[7];
    const float* gw1  = (const float*)d_in[8];
    const float* gw2  = (const float*)d_in[9];
    const float* gw3  = (const float*)d_in[10];
    const float* l2w  = (const float*)d_in[11];
    const float* l2b  = (const float*)d_in[12];
    const float* tg   = (const float*)d_in[13];
    float* out = (float*)d_out;

    const int N = in_sizes[0] / 1600;
    const int NPAIR = N / 2;

    cudaFuncSetAttribute(k_g1,      cudaFuncAttributeMaxDynamicSharedMemorySize, SM_G1 * 4);
    cudaFuncSetAttribute(k_g2,      cudaFuncAttributeMaxDynamicSharedMemorySize, SM_G2 * 4);
    cudaFuncSetAttribute(k_g3_back, cudaFuncAttributeMaxDynamicSharedMemorySize, SM_G3 * 4);

    k_norm<<<NPAIR, 256>>>(x, nl0w, nl0b, affw, l1w, l1b, scw, scb);
    k_g1<<<NPAIR, 256, SM_G1 * 4>>>(gw1, tg);
    k_g2<<<NPAIR, 256, SM_G2 * 4>>>(gw2);
    k_g3_back<<<NPAIR, 256, SM_G3 * 4>>>(gw3, l2w, l2b, tg, out);
}